// round 15
// baseline (speedup 1.0000x reference)
#include <cuda_runtime.h>
#include <cuda_fp16.h>
#include <math.h>
#include <stdint.h>

// ---------------- problem constants ----------------
#define BATCH 4
#define SEQ   2048
#define DMODEL 1024
#define NHEADS 16
#define DK    64
#define MEMT  32
#define TTOT  (SEQ + MEMT)
#define T_PAD 2112
#define NKT   33
#define DFF   4096
#define ROWS  (BATCH * SEQ)
#define XROWS (ROWS + 256)        // pad to multiple of 256 (memory tokens + zeros)
#define NWORDS 66

// ---------------- device scratch ----------------
__device__ __half g_xn [XROWS * DMODEL];
__device__ __half g_q  [BATCH * NHEADS * SEQ   * DK];
__device__ __half g_k  [BATCH * NHEADS * T_PAD * DK];
__device__ __half g_v  [BATCH * NHEADS * T_PAD * DK];
__device__ __half g_ctx[ROWS * DMODEL];
__device__ float  g_x1 [ROWS * DMODEL];
__device__ __half g_xn2[ROWS * DMODEL];
__device__ __half g_h1 [ROWS * DFF];
__device__ float  g_part[BATCH * 16 * DMODEL];
__device__ uint32_t g_mb[SEQ * NWORDS];
__device__ __half g_wqkv[3 * DMODEL * DMODEL];
__device__ __half g_wo  [DMODEL * DMODEL];
__device__ __half g_fw1 [DFF * DMODEL];
__device__ __half g_fw2 [DMODEL * DFF];

// ---------------- helpers ----------------
__device__ __forceinline__ void cp_async16(uint32_t dst, const void* src) {
    asm volatile("cp.async.cg.shared.global [%0], [%1], 16;\n" :: "r"(dst), "l"(src));
}
__device__ __forceinline__ void mma_f16(float* c, const uint32_t* a, const uint32_t* b) {
    asm volatile(
        "mma.sync.aligned.m16n8k16.row.col.f32.f16.f16.f32 "
        "{%0,%1,%2,%3},{%4,%5,%6,%7},{%8,%9},{%0,%1,%2,%3};"
        : "+f"(c[0]), "+f"(c[1]), "+f"(c[2]), "+f"(c[3])
        : "r"(a[0]), "r"(a[1]), "r"(a[2]), "r"(a[3]), "r"(b[0]), "r"(b[1]));
}
__device__ __forceinline__ void ldsm_x4(uint32_t& r0, uint32_t& r1, uint32_t& r2, uint32_t& r3, uint32_t addr) {
    asm volatile("ldmatrix.sync.aligned.m8n8.x4.shared.b16 {%0,%1,%2,%3}, [%4];"
                 : "=r"(r0), "=r"(r1), "=r"(r2), "=r"(r3) : "r"(addr));
}
__device__ __forceinline__ void ldsm_x4_t(uint32_t& r0, uint32_t& r1, uint32_t& r2, uint32_t& r3, uint32_t addr) {
    asm volatile("ldmatrix.sync.aligned.m8n8.x4.trans.shared.b16 {%0,%1,%2,%3}, [%4];"
                 : "=r"(r0), "=r"(r1), "=r"(r2), "=r"(r3) : "r"(addr));
}
__device__ __forceinline__ uint32_t smem_u32(const void* p) {
    return (uint32_t)__cvta_generic_to_shared(p);
}

// ---------------- merged weight transpose + fp16 ----------------
__global__ __launch_bounds__(256) void transpose_all(
    const float* __restrict__ wq, const float* __restrict__ wk,
    const float* __restrict__ wv, const float* __restrict__ wo,
    const float* __restrict__ fw1, const float* __restrict__ fw2,
    __half* __restrict__ dwqkv, __half* __restrict__ dwo,
    __half* __restrict__ dfw1, __half* __restrict__ dfw2)
{
    __shared__ float t[32][33];
    int tb = blockIdx.x;
    const float* src; __half* dst; int K, N, lt;
    if (tb < 3072) {
        int w = tb >> 10; lt = tb & 1023;
        src = (w == 0) ? wq : (w == 1) ? wk : wv;
        dst = dwqkv + (size_t)w * DMODEL * DMODEL;
        K = DMODEL; N = DMODEL;
    } else if (tb < 4096) {
        src = wo;  dst = dwo;  lt = tb - 3072; K = DMODEL; N = DMODEL;
    } else if (tb < 8192) {
        src = fw1; dst = dfw1; lt = tb - 4096; K = DMODEL; N = DFF;
    } else {
        src = fw2; dst = dfw2; lt = tb - 8192; K = DFF; N = DMODEL;
    }
    int ntn = N >> 5;
    int n0 = (lt % ntn) * 32, k0 = (lt / ntn) * 32;
    int tx = threadIdx.x, ty = threadIdx.y;
    #pragma unroll
    for (int i = 0; i < 4; i++)
        t[ty + 8*i][tx] = src[(size_t)(k0 + ty + 8*i) * N + n0 + tx];
    __syncthreads();
    #pragma unroll
    for (int i = 0; i < 4; i++)
        dst[(size_t)(n0 + ty + 8*i) * K + k0 + tx] = __float2half_rn(t[tx][ty + 8*i]);
}

// ---------------- fill memory-token rows of xn (rows ROWS..XROWS) ----------------
__global__ __launch_bounds__(256) void memfill_kernel(
    const float* __restrict__ mt, __half* __restrict__ xn)
{
    int row = blockIdx.x;              // 0..255
    int c4 = threadIdx.x * 4;
    __half2 z = __floats2half2_rn(0.f, 0.f);
    __half2* dst = (__half2*)(xn + (size_t)(ROWS + row) * DMODEL + c4);
    if (row < MEMT) {
        float4 t = *(const float4*)(mt + (size_t)row * DMODEL + c4);
        dst[0] = __floats2half2_rn(t.x, t.y);
        dst[1] = __floats2half2_rn(t.z, t.w);
    } else {
        dst[0] = z;
        dst[1] = z;
    }
}

// ---------------- layer norm (ddof=1); fp16 output ----------------
__global__ __launch_bounds__(256) void ln_kernel(
    const float* __restrict__ x, const float* __restrict__ alpha,
    const float* __restrict__ bias, __half* __restrict__ out)
{
    int row = blockIdx.x;
    int tid = threadIdx.x;
    const float4* xr = (const float4*)(x + (size_t)row * DMODEL);
    float4 v = xr[tid];
    float s  = v.x + v.y + v.z + v.w;
    float ss = v.x*v.x + v.y*v.y + v.z*v.z + v.w*v.w;
    #pragma unroll
    for (int off = 16; off > 0; off >>= 1) {
        s  += __shfl_xor_sync(0xffffffffu, s,  off);
        ss += __shfl_xor_sync(0xffffffffu, ss, off);
    }
    __shared__ float rs[8], rss[8];
    int wid = tid >> 5, lane = tid & 31;
    if (lane == 0) { rs[wid] = s; rss[wid] = ss; }
    __syncthreads();
    float S = 0.f, SS = 0.f;
    #pragma unroll
    for (int w = 0; w < 8; w++) { S += rs[w]; SS += rss[w]; }
    float mean = S * (1.f / DMODEL);
    float var  = (SS - (float)DMODEL * mean * mean) * (1.f / (DMODEL - 1));
    float inv  = 1.f / (sqrtf(fmaxf(var, 0.f)) + 1e-6f);
    float4 a  = ((const float4*)alpha)[tid];
    float4 bb = ((const float4*)bias)[tid];
    __half2* o2 = (__half2*)(out + (size_t)row * DMODEL) + tid * 2;
    o2[0] = __floats2half2_rn(a.x * (v.x - mean) * inv + bb.x,
                              a.y * (v.y - mean) * inv + bb.y);
    o2[1] = __floats2half2_rn(a.z * (v.z - mean) * inv + bb.z,
                              a.w * (v.w - mean) * inv + bb.w);
}

// ---------------- fp16 mma GEMM: 256x128 CTA tile, 3-stage, 1 barrier/iter ----------------
#define EPI_QKV        0
#define EPI_RESID      3
#define EPI_BIAS_RELU  4
#define EPI_BIAS_RESID 5

#define BM 256
#define BN 128
#define BK 64
#define STH 72
#define ATSZ (256 * STH)          // A halves per stage (18432)
#define BTSZ (128 * STH)          // B halves per stage (9216)
#define NSTG 3
#define GEMM_SMEM_BYTES (NSTG * (ATSZ + BTSZ) * 2)   // 165888

template<int EPI>
__global__ __launch_bounds__(256, 1) void gemm_tc(
    const __half* __restrict__ A, const __half* __restrict__ W,
    void* __restrict__ Cp, const float* __restrict__ bias,
    const float* __restrict__ R, __half* __restrict__ C2, __half* __restrict__ C3,
    int M, int N, int K)
{
    extern __shared__ __half sm[];
    __half* As = sm;                       // NSTG stages [256][STH]
    __half* Bs = sm + NSTG * ATSZ;         // NSTG stages [128][STH]

    int tid  = threadIdx.x;
    int warp = tid >> 5, lane = tid & 31;
    int wm = warp & 3;                     // 4 row slabs of 64
    int wn = warp >> 2;                    // 2 col slabs of 64
    int lr = lane >> 2;
    int lc = lane & 3;

    const __half* Abase = A + (size_t)blockIdx.y * BM * K;
    const __half* Wbase = W + (size_t)blockIdx.x * BN * K;

    uint32_t sA = smem_u32(As);
    uint32_t sB = smem_u32(Bs);

    int a_row = (lane & 7) + ((lane >> 3) & 1) * 8;
    int a_kof = (lane >> 4) * 8;
    int b_row = (lane & 7) + ((lane >> 4) & 1) * 8;
    int b_kof = ((lane >> 3) & 1) * 8;

    float acc[4][8][4];
    #pragma unroll
    for (int mt = 0; mt < 4; mt++)
        #pragma unroll
        for (int nt = 0; nt < 8; nt++)
            #pragma unroll
            for (int i = 0; i < 4; i++) acc[mt][nt][i] = 0.f;

    // A: 256 rows x 8 chunks = 2048 chunks (8/thread); B: 128 rows x 8 = 1024 (4/thread)
#define LOAD_STAGE(st, kt) do {                                                   \
        _Pragma("unroll")                                                         \
        for (int l = 0; l < 8; l++) {                                             \
            int fid = tid + l * 256;                                              \
            int r = fid >> 3, c8 = fid & 7;                                       \
            cp_async16(sA + (uint32_t)((st) * ATSZ + r * STH + c8 * 8) * 2,       \
                       Abase + (size_t)r * K + (size_t)(kt) * BK + c8 * 8);       \
        }                                                                         \
        _Pragma("unroll")                                                         \
        for (int l = 0; l < 4; l++) {                                             \
            int fid = tid + l * 256;                                              \
            int r = fid >> 3, c8 = fid & 7;                                       \
            cp_async16(sB + (uint32_t)((st) * BTSZ + r * STH + c8 * 8) * 2,       \
                       Wbase + (size_t)r * K + (size_t)(kt) * BK + c8 * 8);       \
        }                                                                         \
        asm volatile("cp.async.commit_group;");                                   \
    } while (0)

    int NT = K / BK;
    LOAD_STAGE(0, 0);
    LOAD_STAGE(1, 1);

    for (int kt = 0; kt < NT; kt++) {
        int st = kt - (kt / NSTG) * NSTG;
        asm volatile("cp.async.wait_group 1;");
        __syncthreads();
        if (kt + 2 < NT) {
            int sl = st + 2; if (sl >= NSTG) sl -= NSTG;
            LOAD_STAGE(sl, kt + 2);
        } else {
            asm volatile("cp.async.commit_group;");
        }

        uint32_t aS = sA + (uint32_t)(st * ATSZ) * 2;
        uint32_t bS = sB + (uint32_t)(st * BTSZ) * 2;

        #pragma unroll
        for (int ks = 0; ks < 4; ks++) {
            uint32_t af[4][4], bf[8][2];
            #pragma unroll
            for (int mt = 0; mt < 4; mt++) {
                uint32_t addr = aS + (uint32_t)(((wm * 64 + mt * 16 + a_row) * STH)
                                                 + ks * 16 + a_kof) * 2;
                ldsm_x4(af[mt][0], af[mt][1], af[mt][2], af[mt][3], addr);
            }
            #pragma unroll
            for (int nb = 0; nb < 4; nb++) {
                uint32_t addr = bS + (uint32_t)(((wn * 64 + nb * 16 + b_row) * STH)
                                                 + ks * 16 + b_kof) * 2;
                uint32_t r0, r1, r2, r3;
                ldsm_x4(r0, r1, r2, r3, addr);
                bf[nb * 2    ][0] = r0; bf[nb * 2    ][1] = r1;
                bf[nb * 2 + 1][0] = r2; bf[nb * 2 + 1][1] = r3;
            }
            #pragma unroll
            for (int mt = 0; mt < 4; mt++)
                #pragma unroll
                for (int nt = 0; nt < 8; nt++)
                    mma_f16(acc[mt][nt], af[mt], bf[nt]);
        }
    }

    #pragma unroll
    for (int mt = 0; mt < 4; mt++) {
        #pragma unroll
        for (int rg = 0; rg < 2; rg++) {
            int r = blockIdx.y * BM + wm * 64 + mt * 16 + lr + rg * 8;
            #pragma unroll
            for (int nt = 0; nt < 8; nt++) {
                int c = blockIdx.x * BN + wn * 64 + nt * 8 + lc * 2;
                float v0 = acc[mt][nt][rg * 2 + 0];
                float v1 = acc[mt][nt][rg * 2 + 1];
                if (EPI == EPI_QKV) {
                    int sel = c >> 10, cc = c & 1023;
                    int h = cc >> 6, d = cc & 63;
                    __half2 o = __floats2half2_rn(v0, v1);
                    if (r < ROWS) {
                        int b = r >> 11, s2 = r & 2047;
                        if (sel == 0)
                            *(__half2*)((__half*)Cp + ((((size_t)(b * NHEADS + h)) * SEQ + s2) * DK + d)) = o;
                        else if (sel == 1)
                            *(__half2*)(C2 + ((((size_t)(b * NHEADS + h)) * T_PAD + MEMT + s2) * DK + d)) = o;
                        else
                            *(__half2*)(C3 + ((((size_t)(b * NHEADS + h)) * T_PAD + MEMT + s2) * DK + d)) = o;
                    } else {
                        int rr = r - ROWS;
                        if (rr < MEMT && sel > 0) {
                            __half* dstb = (sel == 1) ? C2 : C3;
                            #pragma unroll
                            for (int b = 0; b < BATCH; b++)
                                *(__half2*)(dstb + ((((size_t)(b * NHEADS + h)) * T_PAD + rr) * DK + d)) = o;
                        }
                    }
                } else if (EPI == EPI_RESID) {
                    float2 rr = *(const float2*)(R + (size_t)r * N + c);
                    *(float2*)((float*)Cp + (size_t)r * N + c) = make_float2(v0 + rr.x, v1 + rr.y);
                } else if (EPI == EPI_BIAS_RELU) {
                    float2 bb = *(const float2*)(bias + c);
                    *(__half2*)((__half*)Cp + (size_t)r * N + c) =
                        __floats2half2_rn(fmaxf(v0 + bb.x, 0.f), fmaxf(v1 + bb.y, 0.f));
                } else if (EPI == EPI_BIAS_RESID) {
                    float2 bb = *(const float2*)(bias + c);
                    float2 rr = *(const float2*)(R + (size_t)r * N + c);
                    *(float2*)((float*)Cp + (size_t)r * N + c) = make_float2(v0 + bb.x + rr.x, v1 + bb.y + rr.y);
                }
            }
        }
    }
#undef LOAD_STAGE
}

__global__ __launch_bounds__(256) void padclear_kernel(__half* k, __half* v)
{
    int bh = blockIdx.x;
    size_t base = ((size_t)bh * T_PAD + TTOT) * DK / 2;
    uint32_t* k32 = (uint32_t*)k;
    uint32_t* v32 = (uint32_t*)v;
    for (int i = threadIdx.x; i < (T_PAD - TTOT) * DK / 2; i += 256) {
        k32[base + i] = 0u;
        v32[base + i] = 0u;
    }
}

__global__ void maskbits_kernel(const int* __restrict__ mask, uint32_t* __restrict__ mb)
{
    int s = blockIdx.x;
    int w = threadIdx.x;
    uint32_t bits = 0;
    #pragma unroll 4
    for (int j = 0; j < 32; j++) {
        int t = w * 32 + j;
        if (t < TTOT && mask[(size_t)s * TTOT + t] != 0) bits |= (1u << j);
    }
    mb[(size_t)s * NWORDS + w] = bits;
}

// ---------------- fp16 flash attention (unchanged from R14) ----------------
#define KSTH 72
#define KTSZ (64 * KSTH)
#define PSTH 72
#define ATTN_SMEM_BYTES ((2*KTSZ + 2*KTSZ + 8*16*PSTH) * 2)   // 55296

__global__ __launch_bounds__(256, 2) void attn_tc(
    const __half* __restrict__ q, const __half* __restrict__ k,
    const __half* __restrict__ v, const uint32_t* __restrict__ mb,
    __half* __restrict__ ctx)
{
    extern __shared__ __half smh[];
    __half* ks_ = smh;
    __half* vs_ = ks_ + 2 * KTSZ;
    __half* ps_ = vs_ + 2 * KTSZ;

    int tid  = threadIdx.x;
    int warp = tid >> 5, lane = tid & 31;
    int lr = lane >> 2, lc = lane & 3;
    int bh = blockIdx.y;
    int b  = bh >> 4, h = bh & 15;
    int q0 = blockIdx.x * 128;

    const __half* qb = q + (((size_t)bh) * SEQ + q0) * DK;
    const __half* kb = k + ((size_t)bh) * T_PAD * DK;
    const __half* vb = v + ((size_t)bh) * T_PAD * DK;

    int row0 = warp * 16 + lr;
    int row1 = row0 + 8;
    int grow0 = q0 + row0, grow1 = q0 + row1;
    __half* psw = ps_ + warp * 16 * PSTH;
    uint32_t sP = smem_u32(psw);

    int a_row = (lane & 7) + ((lane >> 3) & 1) * 8;
    int a_kof = (lane >> 4) * 8;
    int b_row = (lane & 7) + ((lane >> 4) & 1) * 8;
    int b_kof = ((lane >> 3) & 1) * 8;

    uint32_t qf[4][4];
    #pragma unroll
    for (int ks = 0; ks < 4; ks++) {
        qf[ks][0] = *(const uint32_t*)(qb + (size_t)row0 * DK + ks * 16 + 2 * lc    );
        qf[ks][1] = *(const uint32_t*)(qb + (size_t)row1 * DK + ks * 16 + 2 * lc    );
        qf[ks][2] = *(const uint32_t*)(qb + (size_t)row0 * DK + ks * 16 + 2 * lc + 8);
        qf[ks][3] = *(const uint32_t*)(qb + (size_t)row1 * DK + ks * 16 + 2 * lc + 8);
    }

    float o[8][4];
    #pragma unroll
    for (int nt = 0; nt < 8; nt++)
        #pragma unroll
        for (int i = 0; i < 4; i++) o[nt][i] = 0.f;

    float m0 = -INFINITY, m1 = -INFINITY, l0 = 0.f, l1 = 0.f;

    uint32_t sK = smem_u32(ks_);
    uint32_t sV = smem_u32(vs_);

#define LOADKV(st, tile) do {                                                       \
        _Pragma("unroll")                                                           \
        for (int l = 0; l < 2; l++) {                                               \
            int fid = tid + l * 256;                                                \
            int r = fid >> 3, c8 = fid & 7;                                         \
            cp_async16(sK + (uint32_t)((st) * KTSZ + r * KSTH + c8 * 8) * 2,        \
                       kb + ((size_t)(tile) * 64 + r) * DK + c8 * 8);               \
            cp_async16(sV + (uint32_t)((st) * KTSZ + r * KSTH + c8 * 8) * 2,        \
                       vb + ((size_t)(tile) * 64 + r) * DK + c8 * 8);               \
        }                                                                           \
        asm volatile("cp.async.commit_group;");                                     \
    } while (0)

    LOADKV(0, 0);

    for (int t = 0; t < NKT; t++) {
        int st = t & 1;
        asm volatile("cp.async.wait_group 0;");
        __syncthreads();
        if (t + 1 < NKT) LOADKV(st ^ 1, t + 1);

        float c[8][4];
        #pragma unroll
        for (int nt = 0; nt < 8; nt++)
            #pragma unroll
            for (int i = 0; i < 4; i++) c[nt][i] = 0.f;

        uint32_t kS = sK + (uint32_t)(st * KTSZ) * 2;
        #pragma unroll
        for (int ks = 0; ks < 4; ks++) {
            #pragma unroll
            for (int nb = 0; nb < 4; nb++) {
                uint32_t addr = kS + (uint32_t)(((nb * 16 + b_row) * KSTH)
                                                 + ks * 16 + b_kof) * 2;
                uint32_t r0, r1, r2, r3;
                ldsm_x4(r0, r1, r2, r3, addr);
                uint32_t bf0[2] = {r0, r1};
                uint32_t bf1[2] = {r2, r3};
                mma_f16(c[nb * 2    ], qf[ks], bf0);
                mma_f16(c[nb * 2 + 1], qf[ks], bf1);
            }
        }

        uint32_t mwA0 = mb[(size_t)grow0 * NWORDS + t * 2    ];
        uint32_t mwA1 = mb[(size_t)grow0 * NWORDS + t * 2 + 1];
        uint32_t mwB0 = mb[(size_t)grow1 * NWORDS + t * 2    ];
        uint32_t mwB1 = mb[(size_t)grow1 * NWORDS + t * 2 + 1];
        bool nomask = __all_sync(0xffffffffu,
            (mwA0 & mwA1 & mwB0 & mwB1) == 0xffffffffu);

        float mx0 = -INFINITY, mx1 = -INFINITY;
        if (nomask) {
            #pragma unroll
            for (int nt = 0; nt < 8; nt++) {
                c[nt][0] *= 0.125f; c[nt][1] *= 0.125f;
                c[nt][2] *= 0.125f; c[nt][3] *= 0.125f;
                mx0 = fmaxf(mx0, fmaxf(c[nt][0], c[nt][1]));
                mx1 = fmaxf(mx1, fmaxf(c[nt][2], c[nt][3]));
            }
        } else {
            #pragma unroll
            for (int nt = 0; nt < 8; nt++) {
                uint32_t wA = (nt < 4) ? mwA0 : mwA1;
                uint32_t wB = (nt < 4) ? mwB0 : mwB1;
                int j = (nt * 8 + 2 * lc) & 31;
                c[nt][0] = ((wA >> j)       & 1u) ? c[nt][0] * 0.125f : -1e9f;
                c[nt][1] = ((wA >> (j + 1)) & 1u) ? c[nt][1] * 0.125f : -1e9f;
                c[nt][2] = ((wB >> j)       & 1u) ? c[nt][2] * 0.125f : -1e9f;
                c[nt][3] = ((wB >> (j + 1)) & 1u) ? c[nt][3] * 0.125f : -1e9f;
                mx0 = fmaxf(mx0, fmaxf(c[nt][0], c[nt][1]));
                mx1 = fmaxf(mx1, fmaxf(c[nt][2], c[nt][3]));
            }
        }
        mx0 = fmaxf(mx0, __shfl_xor_sync(0xffffffffu, mx0, 1));
        mx0 = fmaxf(mx0, __shfl_xor_sync(0xffffffffu, mx0, 2));
        mx1 = fmaxf(mx1, __shfl_xor_sync(0xffffffffu, mx1, 1));
        mx1 = fmaxf(mx1, __shfl_xor_sync(0xffffffffu, mx1, 2));

        float mn0 = fmaxf(m0, mx0);
        float mn1 = fmaxf(m1, mx1);
        float a0 = __expf(m0 - mn0);
        float a1 = __expf(m1 - mn1);
        m0 = mn0; m1 = mn1;

        float s0 = 0.f, s1 = 0.f;
        #pragma unroll
        for (int nt = 0; nt < 8; nt++) {
            int col = nt * 8 + 2 * lc;
            float p00 = __expf(c[nt][0] - mn0);
            float p01 = __expf(c[nt][1] - mn0);
            float p10 = __expf(c[nt][2] - mn1);
            float p11 = __expf(c[nt][3] - mn1);
            s0 += p00 + p01;
            s1 += p10 + p11;
            *(__half2*)(psw + lr       * PSTH + col) = __floats2half2_rn(p00, p01);
            *(__half2*)(psw + (lr + 8) * PSTH + col) = __floats2half2_rn(p10, p11);
        }
        s0 += __shfl_xor_sync(0xffffffffu, s0, 1);
        s0 += __shfl_xor_sync(0xffffffffu, s0, 2);
        s1 += __shfl_xor_sync(0xffffffffu, s1, 1);
        s1 += __shfl_xor_sync(0xffffffffu, s1, 2);
        l0 = l0 * a0 + s0;
        l1 = l1 * a1 + s1;
        __syncwarp();

        #pragma unroll
        for (int nt = 0; nt < 8; nt++) {
            o[nt][0] *= a0; o[nt][1] *= a0;
            o[nt][2] *= a1; o[nt][3] *= a1;
        }
        uint32_t vbase = sV + (uint32_t)(st * KTSZ) * 2;
        #pragma unroll
        for (int ks = 0; ks < 4; ks++) {
            uint32_t af[4];
            uint32_t paddr = sP + (uint32_t)((a_row * PSTH) + ks * 16 + a_kof) * 2;
            ldsm_x4(af[0], af[1], af[2], af[3], paddr);
            #pragma unroll
            for (int np = 0; np < 4; np++) {
                uint32_t addr = vbase
                    + (uint32_t)((ks * 16 + (lane & 15)) * KSTH) * 2
                    + (uint32_t)(np * 16 + ((lane >> 4) << 3)) * 2;
                uint32_t b0, b1, b2, b3;
                ldsm_x4_t(b0, b1, b2, b3, addr);
                uint32_t bf0[2] = {b0, b1};
                uint32_t bf1[2] = {b2, b3};
                mma_f16(o[np * 2    ], af, bf0);
                mma_f16(o[np * 2 + 1], af, bf1);
            }
        }
    }

    float inv0 = 1.f / l0, inv1 = 1.f / l1;
    #pragma unroll
    for (int nt = 0; nt < 8; nt++) {
        int col = h * 64 + nt * 8 + 2 * lc;
        *(__half2*)(ctx + ((size_t)b * SEQ + grow0) * DMODEL + col) =
            __floats2half2_rn(o[nt][0] * inv0, o[nt][1] * inv0);
        *(__half2*)(ctx + ((size_t)b * SEQ + grow1) * DMODEL + col) =
            __floats2half2_rn(o[nt][2] * inv1, o[nt][3] * inv1);
    }
#undef LOADKV
}

// ---------------- new_memory ----------------
__global__ __launch_bounds__(1024) void mem_partial_kernel(
    const float* __restrict__ xo, float* __restrict__ part)
{
    int b = blockIdx.x, cz = blockIdx.y, d = threadIdx.x;
    const float* base = xo + ((size_t)b * SEQ + cz * 128) * DMODEL + d;
    float s = 0.f;
    #pragma unroll 4
    for (int i = 0; i < 128; i++) s += base[(size_t)i * DMODEL];
    part[((size_t)b * 16 + cz) * DMODEL + d] = s;
}

__global__ __launch_bounds__(1024) void mem_final_kernel(
    const float* __restrict__ part, float* __restrict__ memout)
{
    int b = blockIdx.x, d = threadIdx.x;
    float s = 0.f;
    #pragma unroll
    for (int i = 0; i < 16; i++) s += part[((size_t)b * 16 + i) * DMODEL + d];
    float vv = s * (1.f / SEQ);
    #pragma unroll
    for (int m = 0; m < MEMT; m++)
        memout[((size_t)b * MEMT + m) * DMODEL + d] = vv;
}

// ---------------- launch ----------------
extern "C" void kernel_launch(void* const* d_in, const int* in_sizes, int n_in,
                              void* d_out, int out_size)
{
    const float* x    = (const float*)d_in[0];
    const int*   mask = (const int*)  d_in[1];
    const float* mem  = (const float*)d_in[2];
    const float* wq   = (const float*)d_in[3];
    const float* wk   = (const float*)d_in[4];
    const float* wv   = (const float*)d_in[5];
    const float* wo   = (const float*)d_in[6];
    const float* ln1a = (const float*)d_in[7];
    const float* ln1b = (const float*)d_in[8];
    const float* ln2a = (const float*)d_in[9];
    const float* ln2b = (const float*)d_in[10];
    const float* fw1  = (const float*)d_in[11];
    const float* fb1  = (const float*)d_in[12];
    const float* fw2  = (const float*)d_in[13];
    const float* fb2  = (const float*)d_in[14];
    float* out = (float*)d_out;
    float* out_mem = out + (size_t)ROWS * DMODEL;

    void* p;
    __half *xn, *q, *k, *v, *ctx, *xn2, *h1;
    float *x1, *part;
    __half *wqkvt, *wot, *fw1t, *fw2t;
    uint32_t* mb;
    cudaGetSymbolAddress(&p, g_xn);  xn  = (__half*)p;
    cudaGetSymbolAddress(&p, g_q);   q   = (__half*)p;
    cudaGetSymbolAddress(&p, g_k);   k   = (__half*)p;
    cudaGetSymbolAddress(&p, g_v);   v   = (__half*)p;
    cudaGetSymbolAddress(&p, g_ctx); ctx = (__half*)p;
    cudaGetSymbolAddress(&p, g_x1);  x1  = (float*)p;
    cudaGetSymbolAddress(&p, g_xn2); xn2 = (__half*)p;
    cudaGetSymbolAddress(&p, g_h1);  h1  = (__half*)p;
    cudaGetSymbolAddress(&p, g_part);part= (float*)p;
    cudaGetSymbolAddress(&p, g_mb);  mb  = (uint32_t*)p;
    cudaGetSymbolAddress(&p, g_wqkv);wqkvt=(__half*)p;
    cudaGetSymbolAddress(&p, g_wo);  wot = (__half*)p;
    cudaGetSymbolAddress(&p, g_fw1); fw1t= (__half*)p;
    cudaGetSymbolAddress(&p, g_fw2); fw2t= (__half*)p;

    cudaFuncSetAttribute(gemm_tc<EPI_QKV>,       cudaFuncAttributeMaxDynamicSharedMemorySize, GEMM_SMEM_BYTES);
    cudaFuncSetAttribute(gemm_tc<EPI_RESID>,     cudaFuncAttributeMaxDynamicSharedMemorySize, GEMM_SMEM_BYTES);
    cudaFuncSetAttribute(gemm_tc<EPI_BIAS_RELU>, cudaFuncAttributeMaxDynamicSharedMemorySize, GEMM_SMEM_BYTES);
    cudaFuncSetAttribute(gemm_tc<EPI_BIAS_RESID>,cudaFuncAttributeMaxDynamicSharedMemorySize, GEMM_SMEM_BYTES);
    cudaFuncSetAttribute(attn_tc, cudaFuncAttributeMaxDynamicSharedMemorySize, ATTN_SMEM_BYTES);

    ln_kernel<<<ROWS, 256>>>(x, ln1a, ln1b, xn);                       // 1
    maskbits_kernel<<<SEQ, NWORDS>>>(mask, mb);                        // 2
    padclear_kernel<<<BATCH * NHEADS, 256>>>(k, v);                    // 3
    memfill_kernel<<<256, 256>>>(mem, xn);                             // 4
    transpose_all<<<12288, dim3(32, 8)>>>(wq, wk, wv, wo, fw1, fw2,    // 5
                                          wqkvt, wot, fw1t, fw2t);

    // fused QKV + memory-token projection, 256-row tiles
    gemm_tc<EPI_QKV><<<dim3(3*DMODEL/BN, XROWS/BM), 256, GEMM_SMEM_BYTES>>>(  // 6 <- profiled
        xn, wqkvt, q, nullptr, nullptr, k, v, XROWS, 3*DMODEL, DMODEL);

    attn_tc<<<dim3(SEQ/128, BATCH*NHEADS), 256, ATTN_SMEM_BYTES>>>(q, k, v, mb, ctx);

    gemm_tc<EPI_RESID><<<dim3(DMODEL/BN, ROWS/BM), 256, GEMM_SMEM_BYTES>>>(
        ctx, wot, x1, nullptr, x, nullptr, nullptr, ROWS, DMODEL, DMODEL);

    ln_kernel<<<ROWS, 256>>>(x1, ln2a, ln2b, xn2);

    gemm_tc<EPI_BIAS_RELU><<<dim3(DFF/BN, ROWS/BM), 256, GEMM_SMEM_BYTES>>>(
        xn2, fw1t, h1, fb1, nullptr, nullptr, nullptr, ROWS, DFF, DMODEL);
    gemm_tc<EPI_BIAS_RESID><<<dim3(DMODEL/BN, ROWS/BM), 256, GEMM_SMEM_BYTES>>>(
        h1, fw2t, out, fb2, x1, nullptr, nullptr, ROWS, DMODEL, DFF);

    mem_partial_kernel<<<dim3(BATCH, 16), 1024>>>(out, part);
    mem_final_kernel<<<BATCH, 1024>>>(part, out_mem);
}

// round 16
// speedup vs baseline: 1.0553x; 1.0553x over previous
#include <cuda_runtime.h>
#include <cuda_fp16.h>
#include <math.h>
#include <stdint.h>

// ---------------- problem constants ----------------
#define BATCH 4
#define SEQ   2048
#define DMODEL 1024
#define NHEADS 16
#define DK    64
#define MEMT  32
#define TTOT  (SEQ + MEMT)
#define T_PAD 2112
#define NKT   33
#define DFF   4096
#define ROWS  (BATCH * SEQ)
#define XROWS (ROWS + 128)        // +1 M-block for memory tokens
#define NWORDS 66

// ---------------- device scratch ----------------
__device__ __half g_xn [XROWS * DMODEL];
__device__ __half g_q  [BATCH * NHEADS * SEQ   * DK];
__device__ __half g_k  [BATCH * NHEADS * T_PAD * DK];
__device__ __half g_v  [BATCH * NHEADS * T_PAD * DK];
__device__ __half g_ctx[ROWS * DMODEL];
__device__ float  g_x1 [ROWS * DMODEL];
__device__ __half g_xn2[ROWS * DMODEL];
__device__ __half g_h1 [ROWS * DFF];
__device__ float  g_part[BATCH * 16 * DMODEL];
__device__ uint32_t g_mb[SEQ * NWORDS];
__device__ __half g_wqkv[3 * DMODEL * DMODEL];
__device__ __half g_wo  [DMODEL * DMODEL];
__device__ __half g_fw1 [DFF * DMODEL];
__device__ __half g_fw2 [DMODEL * DFF];

// ---------------- helpers ----------------
__device__ __forceinline__ void cp_async16(uint32_t dst, const void* src) {
    asm volatile("cp.async.cg.shared.global [%0], [%1], 16;\n" :: "r"(dst), "l"(src));
}
__device__ __forceinline__ void cp_async16_ca(uint32_t dst, const void* src) {
    asm volatile("cp.async.ca.shared.global [%0], [%1], 16;\n" :: "r"(dst), "l"(src));
}
__device__ __forceinline__ void mma_f16(float* c, const uint32_t* a, const uint32_t* b) {
    asm volatile(
        "mma.sync.aligned.m16n8k16.row.col.f32.f16.f16.f32 "
        "{%0,%1,%2,%3},{%4,%5,%6,%7},{%8,%9},{%0,%1,%2,%3};"
        : "+f"(c[0]), "+f"(c[1]), "+f"(c[2]), "+f"(c[3])
        : "r"(a[0]), "r"(a[1]), "r"(a[2]), "r"(a[3]), "r"(b[0]), "r"(b[1]));
}
__device__ __forceinline__ void ldsm_x4(uint32_t& r0, uint32_t& r1, uint32_t& r2, uint32_t& r3, uint32_t addr) {
    asm volatile("ldmatrix.sync.aligned.m8n8.x4.shared.b16 {%0,%1,%2,%3}, [%4];"
                 : "=r"(r0), "=r"(r1), "=r"(r2), "=r"(r3) : "r"(addr));
}
__device__ __forceinline__ void ldsm_x4_t(uint32_t& r0, uint32_t& r1, uint32_t& r2, uint32_t& r3, uint32_t addr) {
    asm volatile("ldmatrix.sync.aligned.m8n8.x4.trans.shared.b16 {%0,%1,%2,%3}, [%4];"
                 : "=r"(r0), "=r"(r1), "=r"(r2), "=r"(r3) : "r"(addr));
}
__device__ __forceinline__ uint32_t smem_u32(const void* p) {
    return (uint32_t)__cvta_generic_to_shared(p);
}

// ---------------- merged weight transpose + fp16 ----------------
__global__ __launch_bounds__(256) void transpose_all(
    const float* __restrict__ wq, const float* __restrict__ wk,
    const float* __restrict__ wv, const float* __restrict__ wo,
    const float* __restrict__ fw1, const float* __restrict__ fw2,
    __half* __restrict__ dwqkv, __half* __restrict__ dwo,
    __half* __restrict__ dfw1, __half* __restrict__ dfw2)
{
    __shared__ float t[32][33];
    int tb = blockIdx.x;
    const float* src; __half* dst; int K, N, lt;
    if (tb < 3072) {
        int w = tb >> 10; lt = tb & 1023;
        src = (w == 0) ? wq : (w == 1) ? wk : wv;
        dst = dwqkv + (size_t)w * DMODEL * DMODEL;
        K = DMODEL; N = DMODEL;
    } else if (tb < 4096) {
        src = wo;  dst = dwo;  lt = tb - 3072; K = DMODEL; N = DMODEL;
    } else if (tb < 8192) {
        src = fw1; dst = dfw1; lt = tb - 4096; K = DMODEL; N = DFF;
    } else {
        src = fw2; dst = dfw2; lt = tb - 8192; K = DFF; N = DMODEL;
    }
    int ntn = N >> 5;
    int n0 = (lt % ntn) * 32, k0 = (lt / ntn) * 32;
    int tx = threadIdx.x, ty = threadIdx.y;
    #pragma unroll
    for (int i = 0; i < 4; i++)
        t[ty + 8*i][tx] = src[(size_t)(k0 + ty + 8*i) * N + n0 + tx];
    __syncthreads();
    #pragma unroll
    for (int i = 0; i < 4; i++)
        dst[(size_t)(n0 + ty + 8*i) * K + k0 + tx] = __float2half_rn(t[tx][ty + 8*i]);
}

// ---------------- fill memory-token rows of xn ----------------
__global__ __launch_bounds__(256) void memfill_kernel(
    const float* __restrict__ mt, __half* __restrict__ xn)
{
    int row = blockIdx.x;              // 0..127
    int c4 = threadIdx.x * 4;
    __half2 z = __floats2half2_rn(0.f, 0.f);
    __half2* dst = (__half2*)(xn + (size_t)(ROWS + row) * DMODEL + c4);
    if (row < MEMT) {
        float4 t = *(const float4*)(mt + (size_t)row * DMODEL + c4);
        dst[0] = __floats2half2_rn(t.x, t.y);
        dst[1] = __floats2half2_rn(t.z, t.w);
    } else {
        dst[0] = z;
        dst[1] = z;
    }
}

// ---------------- layer norm (ddof=1); fp16 output ----------------
__global__ __launch_bounds__(256) void ln_kernel(
    const float* __restrict__ x, const float* __restrict__ alpha,
    const float* __restrict__ bias, __half* __restrict__ out)
{
    int row = blockIdx.x;
    int tid = threadIdx.x;
    const float4* xr = (const float4*)(x + (size_t)row * DMODEL);
    float4 v = xr[tid];
    float s  = v.x + v.y + v.z + v.w;
    float ss = v.x*v.x + v.y*v.y + v.z*v.z + v.w*v.w;
    #pragma unroll
    for (int off = 16; off > 0; off >>= 1) {
        s  += __shfl_xor_sync(0xffffffffu, s,  off);
        ss += __shfl_xor_sync(0xffffffffu, ss, off);
    }
    __shared__ float rs[8], rss[8];
    int wid = tid >> 5, lane = tid & 31;
    if (lane == 0) { rs[wid] = s; rss[wid] = ss; }
    __syncthreads();
    float S = 0.f, SS = 0.f;
    #pragma unroll
    for (int w = 0; w < 8; w++) { S += rs[w]; SS += rss[w]; }
    float mean = S * (1.f / DMODEL);
    float var  = (SS - (float)DMODEL * mean * mean) * (1.f / (DMODEL - 1));
    float inv  = 1.f / (sqrtf(fmaxf(var, 0.f)) + 1e-6f);
    float4 a  = ((const float4*)alpha)[tid];
    float4 bb = ((const float4*)bias)[tid];
    __half2* o2 = (__half2*)(out + (size_t)row * DMODEL) + tid * 2;
    o2[0] = __floats2half2_rn(a.x * (v.x - mean) * inv + bb.x,
                              a.y * (v.y - mean) * inv + bb.y);
    o2[1] = __floats2half2_rn(a.z * (v.z - mean) * inv + bb.z,
                              a.w * (v.w - mean) * inv + bb.w);
}

// ---------------- fp16 mma GEMM: 128x128 CTA tile (R14 config), 3-stage ----------------
#define EPI_QKV        0
#define EPI_RESID      3
#define EPI_BIAS_RELU  4
#define EPI_BIAS_RESID 5

#define BM 128
#define BN 128
#define BK 64
#define STH 72
#define TSZ (128 * STH)
#define NSTG 3
#define GEMM_SMEM_BYTES (NSTG * 2 * TSZ * 2)   // 110592

template<int EPI>
__global__ __launch_bounds__(256, 2) void gemm_tc(
    const __half* __restrict__ A, const __half* __restrict__ W,
    void* __restrict__ Cp, const float* __restrict__ bias,
    const float* __restrict__ R, __half* __restrict__ C2, __half* __restrict__ C3,
    int M, int N, int K)
{
    extern __shared__ __half sm[];
    __half* As = sm;
    __half* Bs = sm + NSTG * TSZ;

    int tid  = threadIdx.x;
    int warp = tid >> 5, lane = tid & 31;
    int wm = warp & 1;
    int wn = warp >> 1;
    int lr = lane >> 2;
    int lc = lane & 3;

    const __half* Abase = A + (size_t)blockIdx.y * BM * K;
    const __half* Wbase = W + (size_t)blockIdx.x * BN * K;

    uint32_t sA = smem_u32(As);
    uint32_t sB = smem_u32(Bs);

    int a_row = (lane & 7) + ((lane >> 3) & 1) * 8;
    int a_kof = (lane >> 4) * 8;
    int b_row = (lane & 7) + ((lane >> 4) & 1) * 8;
    int b_kof = ((lane >> 3) & 1) * 8;

    float acc[4][4][4];
    #pragma unroll
    for (int mt = 0; mt < 4; mt++)
        #pragma unroll
        for (int nt = 0; nt < 4; nt++)
            #pragma unroll
            for (int i = 0; i < 4; i++) acc[mt][nt][i] = 0.f;

#define LOAD_STAGE(st, kt) do {                                                   \
        _Pragma("unroll")                                                         \
        for (int l = 0; l < 4; l++) {                                             \
            int fid = tid + l * 256;                                              \
            int r = fid >> 3, c8 = fid & 7;                                       \
            cp_async16(sA + (uint32_t)((st) * TSZ + r * STH + c8 * 8) * 2,        \
                       Abase + (size_t)r * K + (size_t)(kt) * BK + c8 * 8);       \
        }                                                                         \
        _Pragma("unroll")                                                         \
        for (int l = 0; l < 4; l++) {                                             \
            int fid = tid + l * 256;                                              \
            int r = fid >> 3, c8 = fid & 7;                                       \
            cp_async16_ca(sB + (uint32_t)((st) * TSZ + r * STH + c8 * 8) * 2,     \
                       Wbase + (size_t)r * K + (size_t)(kt) * BK + c8 * 8);       \
        }                                                                         \
        asm volatile("cp.async.commit_group;");                                   \
    } while (0)

    int NT = K / BK;
    LOAD_STAGE(0, 0);
    LOAD_STAGE(1, 1);

    for (int kt = 0; kt < NT; kt++) {
        int st = kt - (kt / NSTG) * NSTG;
        asm volatile("cp.async.wait_group 1;");
        __syncthreads();
        if (kt + 2 < NT) {
            int sl = st + 2; if (sl >= NSTG) sl -= NSTG;
            LOAD_STAGE(sl, kt + 2);
        } else {
            asm volatile("cp.async.commit_group;");
        }

        uint32_t aS = sA + (uint32_t)(st * TSZ) * 2;
        uint32_t bS = sB + (uint32_t)(st * TSZ) * 2;

        #pragma unroll
        for (int ks = 0; ks < 4; ks++) {
            uint32_t af[4][4], bf[4][2];
            #pragma unroll
            for (int mt = 0; mt < 4; mt++) {
                uint32_t addr = aS + (uint32_t)(((wm * 64 + mt * 16 + a_row) * STH)
                                                 + ks * 16 + a_kof) * 2;
                ldsm_x4(af[mt][0], af[mt][1], af[mt][2], af[mt][3], addr);
            }
            #pragma unroll
            for (int nb = 0; nb < 2; nb++) {
                uint32_t addr = bS + (uint32_t)(((wn * 32 + nb * 16 + b_row) * STH)
                                                 + ks * 16 + b_kof) * 2;
                uint32_t r0, r1, r2, r3;
                ldsm_x4(r0, r1, r2, r3, addr);
                bf[nb * 2    ][0] = r0; bf[nb * 2    ][1] = r1;
                bf[nb * 2 + 1][0] = r2; bf[nb * 2 + 1][1] = r3;
            }
            #pragma unroll
            for (int mt = 0; mt < 4; mt++)
                #pragma unroll
                for (int nt = 0; nt < 4; nt++)
                    mma_f16(acc[mt][nt], af[mt], bf[nt]);
        }
    }

    #pragma unroll
    for (int mt = 0; mt < 4; mt++) {
        #pragma unroll
        for (int rg = 0; rg < 2; rg++) {
            int r = blockIdx.y * BM + wm * 64 + mt * 16 + lr + rg * 8;
            #pragma unroll
            for (int nt = 0; nt < 4; nt++) {
                int c = blockIdx.x * BN + wn * 32 + nt * 8 + lc * 2;
                float v0 = acc[mt][nt][rg * 2 + 0];
                float v1 = acc[mt][nt][rg * 2 + 1];
                if (EPI == EPI_QKV) {
                    int sel = c >> 10, cc = c & 1023;
                    int h = cc >> 6, d = cc & 63;
                    __half2 o = __floats2half2_rn(v0, v1);
                    if (r < ROWS) {
                        int b = r >> 11, s2 = r & 2047;
                        if (sel == 0)
                            *(__half2*)((__half*)Cp + ((((size_t)(b * NHEADS + h)) * SEQ + s2) * DK + d)) = o;
                        else if (sel == 1)
                            *(__half2*)(C2 + ((((size_t)(b * NHEADS + h)) * T_PAD + MEMT + s2) * DK + d)) = o;
                        else
                            *(__half2*)(C3 + ((((size_t)(b * NHEADS + h)) * T_PAD + MEMT + s2) * DK + d)) = o;
                    } else {
                        int rr = r - ROWS;
                        if (rr < MEMT && sel > 0) {
                            __half* dstb = (sel == 1) ? C2 : C3;
                            #pragma unroll
                            for (int b = 0; b < BATCH; b++)
                                *(__half2*)(dstb + ((((size_t)(b * NHEADS + h)) * T_PAD + rr) * DK + d)) = o;
                        }
                    }
                } else if (EPI == EPI_RESID) {
                    float2 rr = *(const float2*)(R + (size_t)r * N + c);
                    *(float2*)((float*)Cp + (size_t)r * N + c) = make_float2(v0 + rr.x, v1 + rr.y);
                } else if (EPI == EPI_BIAS_RELU) {
                    float2 bb = *(const float2*)(bias + c);
                    *(__half2*)((__half*)Cp + (size_t)r * N + c) =
                        __floats2half2_rn(fmaxf(v0 + bb.x, 0.f), fmaxf(v1 + bb.y, 0.f));
                } else if (EPI == EPI_BIAS_RESID) {
                    float2 bb = *(const float2*)(bias + c);
                    float2 rr = *(const float2*)(R + (size_t)r * N + c);
                    *(float2*)((float*)Cp + (size_t)r * N + c) = make_float2(v0 + bb.x + rr.x, v1 + bb.y + rr.y);
                }
            }
        }
    }
#undef LOAD_STAGE
}

__global__ __launch_bounds__(256) void padclear_kernel(__half* k, __half* v)
{
    int bh = blockIdx.x;
    size_t base = ((size_t)bh * T_PAD + TTOT) * DK / 2;
    uint32_t* k32 = (uint32_t*)k;
    uint32_t* v32 = (uint32_t*)v;
    for (int i = threadIdx.x; i < (T_PAD - TTOT) * DK / 2; i += 256) {
        k32[base + i] = 0u;
        v32[base + i] = 0u;
    }
}

__global__ void maskbits_kernel(const int* __restrict__ mask, uint32_t* __restrict__ mb)
{
    int s = blockIdx.x;
    int w = threadIdx.x;
    uint32_t bits = 0;
    #pragma unroll 4
    for (int j = 0; j < 32; j++) {
        int t = w * 32 + j;
        if (t < TTOT && mask[(size_t)s * TTOT + t] != 0) bits |= (1u << j);
    }
    mb[(size_t)s * NWORDS + w] = bits;
}

// ---------------- fp16 flash attention (R14 config) ----------------
#define KSTH 72
#define KTSZ (64 * KSTH)
#define PSTH 72
#define ATTN_SMEM_BYTES ((2*KTSZ + 2*KTSZ + 8*16*PSTH) * 2)   // 55296

__global__ __launch_bounds__(256, 2) void attn_tc(
    const __half* __restrict__ q, const __half* __restrict__ k,
    const __half* __restrict__ v, const uint32_t* __restrict__ mb,
    __half* __restrict__ ctx)
{
    extern __shared__ __half smh[];
    __half* ks_ = smh;
    __half* vs_ = ks_ + 2 * KTSZ;
    __half* ps_ = vs_ + 2 * KTSZ;

    int tid  = threadIdx.x;
    int warp = tid >> 5, lane = tid & 31;
    int lr = lane >> 2, lc = lane & 3;
    int bh = blockIdx.y;
    int b  = bh >> 4, h = bh & 15;
    int q0 = blockIdx.x * 128;

    const __half* qb = q + (((size_t)bh) * SEQ + q0) * DK;
    const __half* kb = k + ((size_t)bh) * T_PAD * DK;
    const __half* vb = v + ((size_t)bh) * T_PAD * DK;

    int row0 = warp * 16 + lr;
    int row1 = row0 + 8;
    int grow0 = q0 + row0, grow1 = q0 + row1;
    __half* psw = ps_ + warp * 16 * PSTH;
    uint32_t sP = smem_u32(psw);

    int a_row = (lane & 7) + ((lane >> 3) & 1) * 8;
    int a_kof = (lane >> 4) * 8;
    int b_row = (lane & 7) + ((lane >> 4) & 1) * 8;
    int b_kof = ((lane >> 3) & 1) * 8;

    uint32_t qf[4][4];
    #pragma unroll
    for (int ks = 0; ks < 4; ks++) {
        qf[ks][0] = *(const uint32_t*)(qb + (size_t)row0 * DK + ks * 16 + 2 * lc    );
        qf[ks][1] = *(const uint32_t*)(qb + (size_t)row1 * DK + ks * 16 + 2 * lc    );
        qf[ks][2] = *(const uint32_t*)(qb + (size_t)row0 * DK + ks * 16 + 2 * lc + 8);
        qf[ks][3] = *(const uint32_t*)(qb + (size_t)row1 * DK + ks * 16 + 2 * lc + 8);
    }

    float o[8][4];
    #pragma unroll
    for (int nt = 0; nt < 8; nt++)
        #pragma unroll
        for (int i = 0; i < 4; i++) o[nt][i] = 0.f;

    float m0 = -INFINITY, m1 = -INFINITY, l0 = 0.f, l1 = 0.f;

    uint32_t sK = smem_u32(ks_);
    uint32_t sV = smem_u32(vs_);

#define LOADKV(st, tile) do {                                                       \
        _Pragma("unroll")                                                           \
        for (int l = 0; l < 2; l++) {                                               \
            int fid = tid + l * 256;                                                \
            int r = fid >> 3, c8 = fid & 7;                                         \
            cp_async16(sK + (uint32_t)((st) * KTSZ + r * KSTH + c8 * 8) * 2,        \
                       kb + ((size_t)(tile) * 64 + r) * DK + c8 * 8);               \
            cp_async16(sV + (uint32_t)((st) * KTSZ + r * KSTH + c8 * 8) * 2,        \
                       vb + ((size_t)(tile) * 64 + r) * DK + c8 * 8);               \
        }                                                                           \
        asm volatile("cp.async.commit_group;");                                     \
    } while (0)

    LOADKV(0, 0);

    for (int t = 0; t < NKT; t++) {
        int st = t & 1;
        asm volatile("cp.async.wait_group 0;");
        __syncthreads();
        if (t + 1 < NKT) LOADKV(st ^ 1, t + 1);

        float c[8][4];
        #pragma unroll
        for (int nt = 0; nt < 8; nt++)
            #pragma unroll
            for (int i = 0; i < 4; i++) c[nt][i] = 0.f;

        uint32_t kS = sK + (uint32_t)(st * KTSZ) * 2;
        #pragma unroll
        for (int ks = 0; ks < 4; ks++) {
            #pragma unroll
            for (int nb = 0; nb < 4; nb++) {
                uint32_t addr = kS + (uint32_t)(((nb * 16 + b_row) * KSTH)
                                                 + ks * 16 + b_kof) * 2;
                uint32_t r0, r1, r2, r3;
                ldsm_x4(r0, r1, r2, r3, addr);
                uint32_t bf0[2] = {r0, r1};
                uint32_t bf1[2] = {r2, r3};
                mma_f16(c[nb * 2    ], qf[ks], bf0);
                mma_f16(c[nb * 2 + 1], qf[ks], bf1);
            }
        }

        uint32_t mwA0 = mb[(size_t)grow0 * NWORDS + t * 2    ];
        uint32_t mwA1 = mb[(size_t)grow0 * NWORDS + t * 2 + 1];
        uint32_t mwB0 = mb[(size_t)grow1 * NWORDS + t * 2    ];
        uint32_t mwB1 = mb[(size_t)grow1 * NWORDS + t * 2 + 1];
        bool nomask = __all_sync(0xffffffffu,
            (mwA0 & mwA1 & mwB0 & mwB1) == 0xffffffffu);

        float mx0 = -INFINITY, mx1 = -INFINITY;
        if (nomask) {
            #pragma unroll
            for (int nt = 0; nt < 8; nt++) {
                c[nt][0] *= 0.125f; c[nt][1] *= 0.125f;
                c[nt][2] *= 0.125f; c[nt][3] *= 0.125f;
                mx0 = fmaxf(mx0, fmaxf(c[nt][0], c[nt][1]));
                mx1 = fmaxf(mx1, fmaxf(c[nt][2], c[nt][3]));
            }
        } else {
            #pragma unroll
            for (int nt = 0; nt < 8; nt++) {
                uint32_t wA = (nt < 4) ? mwA0 : mwA1;
                uint32_t wB = (nt < 4) ? mwB0 : mwB1;
                int j = (nt * 8 + 2 * lc) & 31;
                c[nt][0] = ((wA >> j)       & 1u) ? c[nt][0] * 0.125f : -1e9f;
                c[nt][1] = ((wA >> (j + 1)) & 1u) ? c[nt][1] * 0.125f : -1e9f;
                c[nt][2] = ((wB >> j)       & 1u) ? c[nt][2] * 0.125f : -1e9f;
                c[nt][3] = ((wB >> (j + 1)) & 1u) ? c[nt][3] * 0.125f : -1e9f;
                mx0 = fmaxf(mx0, fmaxf(c[nt][0], c[nt][1]));
                mx1 = fmaxf(mx1, fmaxf(c[nt][2], c[nt][3]));
            }
        }
        mx0 = fmaxf(mx0, __shfl_xor_sync(0xffffffffu, mx0, 1));
        mx0 = fmaxf(mx0, __shfl_xor_sync(0xffffffffu, mx0, 2));
        mx1 = fmaxf(mx1, __shfl_xor_sync(0xffffffffu, mx1, 1));
        mx1 = fmaxf(mx1, __shfl_xor_sync(0xffffffffu, mx1, 2));

        float mn0 = fmaxf(m0, mx0);
        float mn1 = fmaxf(m1, mx1);
        float a0 = __expf(m0 - mn0);
        float a1 = __expf(m1 - mn1);
        m0 = mn0; m1 = mn1;

        float s0 = 0.f, s1 = 0.f;
        #pragma unroll
        for (int nt = 0; nt < 8; nt++) {
            int col = nt * 8 + 2 * lc;
            float p00 = __expf(c[nt][0] - mn0);
            float p01 = __expf(c[nt][1] - mn0);
            float p10 = __expf(c[nt][2] - mn1);
            float p11 = __expf(c[nt][3] - mn1);
            s0 += p00 + p01;
            s1 += p10 + p11;
            *(__half2*)(psw + lr       * PSTH + col) = __floats2half2_rn(p00, p01);
            *(__half2*)(psw + (lr + 8) * PSTH + col) = __floats2half2_rn(p10, p11);
        }
        s0 += __shfl_xor_sync(0xffffffffu, s0, 1);
        s0 += __shfl_xor_sync(0xffffffffu, s0, 2);
        s1 += __shfl_xor_sync(0xffffffffu, s1, 1);
        s1 += __shfl_xor_sync(0xffffffffu, s1, 2);
        l0 = l0 * a0 + s0;
        l1 = l1 * a1 + s1;
        __syncwarp();

        #pragma unroll
        for (int nt = 0; nt < 8; nt++) {
            o[nt][0] *= a0; o[nt][1] *= a0;
            o[nt][2] *= a1; o[nt][3] *= a1;
        }
        uint32_t vbase = sV + (uint32_t)(st * KTSZ) * 2;
        #pragma unroll
        for (int ks = 0; ks < 4; ks++) {
            uint32_t af[4];
            uint32_t paddr = sP + (uint32_t)((a_row * PSTH) + ks * 16 + a_kof) * 2;
            ldsm_x4(af[0], af[1], af[2], af[3], paddr);
            #pragma unroll
            for (int np = 0; np < 4; np++) {
                uint32_t addr = vbase
                    + (uint32_t)((ks * 16 + (lane & 15)) * KSTH) * 2
                    + (uint32_t)(np * 16 + ((lane >> 4) << 3)) * 2;
                uint32_t b0, b1, b2, b3;
                ldsm_x4_t(b0, b1, b2, b3, addr);
                uint32_t bf0[2] = {b0, b1};
                uint32_t bf1[2] = {b2, b3};
                mma_f16(o[np * 2    ], af, bf0);
                mma_f16(o[np * 2 + 1], af, bf1);
            }
        }
    }

    float inv0 = 1.f / l0, inv1 = 1.f / l1;
    #pragma unroll
    for (int nt = 0; nt < 8; nt++) {
        int col = h * 64 + nt * 8 + 2 * lc;
        *(__half2*)(ctx + ((size_t)b * SEQ + grow0) * DMODEL + col) =
            __floats2half2_rn(o[nt][0] * inv0, o[nt][1] * inv0);
        *(__half2*)(ctx + ((size_t)b * SEQ + grow1) * DMODEL + col) =
            __floats2half2_rn(o[nt][2] * inv1, o[nt][3] * inv1);
    }
#undef LOADKV
}

// ---------------- new_memory ----------------
__global__ __launch_bounds__(1024) void mem_partial_kernel(
    const float* __restrict__ xo, float* __restrict__ part)
{
    int b = blockIdx.x, cz = blockIdx.y, d = threadIdx.x;
    const float* base = xo + ((size_t)b * SEQ + cz * 128) * DMODEL + d;
    float s = 0.f;
    #pragma unroll 4
    for (int i = 0; i < 128; i++) s += base[(size_t)i * DMODEL];
    part[((size_t)b * 16 + cz) * DMODEL + d] = s;
}

__global__ __launch_bounds__(1024) void mem_final_kernel(
    const float* __restrict__ part, float* __restrict__ memout)
{
    int b = blockIdx.x, d = threadIdx.x;
    float s = 0.f;
    #pragma unroll
    for (int i = 0; i < 16; i++) s += part[((size_t)b * 16 + i) * DMODEL + d];
    float vv = s * (1.f / SEQ);
    #pragma unroll
    for (int m = 0; m < MEMT; m++)
        memout[((size_t)b * MEMT + m) * DMODEL + d] = vv;
}

// ---------------- launch ----------------
extern "C" void kernel_launch(void* const* d_in, const int* in_sizes, int n_in,
                              void* d_out, int out_size)
{
    const float* x    = (const float*)d_in[0];
    const int*   mask = (const int*)  d_in[1];
    const float* mem  = (const float*)d_in[2];
    const float* wq   = (const float*)d_in[3];
    const float* wk   = (const float*)d_in[4];
    const float* wv   = (const float*)d_in[5];
    const float* wo   = (const float*)d_in[6];
    const float* ln1a = (const float*)d_in[7];
    const float* ln1b = (const float*)d_in[8];
    const float* ln2a = (const float*)d_in[9];
    const float* ln2b = (const float*)d_in[10];
    const float* fw1  = (const float*)d_in[11];
    const float* fb1  = (const float*)d_in[12];
    const float* fw2  = (const float*)d_in[13];
    const float* fb2  = (const float*)d_in[14];
    float* out = (float*)d_out;
    float* out_mem = out + (size_t)ROWS * DMODEL;

    void* p;
    __half *xn, *q, *k, *v, *ctx, *xn2, *h1;
    float *x1, *part;
    __half *wqkvt, *wot, *fw1t, *fw2t;
    uint32_t* mb;
    cudaGetSymbolAddress(&p, g_xn);  xn  = (__half*)p;
    cudaGetSymbolAddress(&p, g_q);   q   = (__half*)p;
    cudaGetSymbolAddress(&p, g_k);   k   = (__half*)p;
    cudaGetSymbolAddress(&p, g_v);   v   = (__half*)p;
    cudaGetSymbolAddress(&p, g_ctx); ctx = (__half*)p;
    cudaGetSymbolAddress(&p, g_x1);  x1  = (float*)p;
    cudaGetSymbolAddress(&p, g_xn2); xn2 = (__half*)p;
    cudaGetSymbolAddress(&p, g_h1);  h1  = (__half*)p;
    cudaGetSymbolAddress(&p, g_part);part= (float*)p;
    cudaGetSymbolAddress(&p, g_mb);  mb  = (uint32_t*)p;
    cudaGetSymbolAddress(&p, g_wqkv);wqkvt=(__half*)p;
    cudaGetSymbolAddress(&p, g_wo);  wot = (__half*)p;
    cudaGetSymbolAddress(&p, g_fw1); fw1t= (__half*)p;
    cudaGetSymbolAddress(&p, g_fw2); fw2t= (__half*)p;

    cudaFuncSetAttribute(gemm_tc<EPI_QKV>,       cudaFuncAttributeMaxDynamicSharedMemorySize, GEMM_SMEM_BYTES);
    cudaFuncSetAttribute(gemm_tc<EPI_RESID>,     cudaFuncAttributeMaxDynamicSharedMemorySize, GEMM_SMEM_BYTES);
    cudaFuncSetAttribute(gemm_tc<EPI_BIAS_RELU>, cudaFuncAttributeMaxDynamicSharedMemorySize, GEMM_SMEM_BYTES);
    cudaFuncSetAttribute(gemm_tc<EPI_BIAS_RESID>,cudaFuncAttributeMaxDynamicSharedMemorySize, GEMM_SMEM_BYTES);
    cudaFuncSetAttribute(attn_tc, cudaFuncAttributeMaxDynamicSharedMemorySize, ATTN_SMEM_BYTES);

    ln_kernel<<<ROWS, 256>>>(x, ln1a, ln1b, xn);                       // 1
    maskbits_kernel<<<SEQ, NWORDS>>>(mask, mb);                        // 2
    padclear_kernel<<<BATCH * NHEADS, 256>>>(k, v);                    // 3
    memfill_kernel<<<128, 256>>>(mem, xn);                             // 4
    transpose_all<<<12288, dim3(32, 8)>>>(wq, wk, wv, wo, fw1, fw2,    // 5
                                          wqkvt, wot, fw1t, fw2t);

    gemm_tc<EPI_QKV><<<dim3(3*DMODEL/BN, XROWS/BM), 256, GEMM_SMEM_BYTES>>>(  // 6 <- profiled
        xn, wqkvt, q, nullptr, nullptr, k, v, XROWS, 3*DMODEL, DMODEL);

    attn_tc<<<dim3(SEQ/128, BATCH*NHEADS), 256, ATTN_SMEM_BYTES>>>(q, k, v, mb, ctx);

    gemm_tc<EPI_RESID><<<dim3(DMODEL/BN, ROWS/BM), 256, GEMM_SMEM_BYTES>>>(
        ctx, wot, x1, nullptr, x, nullptr, nullptr, ROWS, DMODEL, DMODEL);

    ln_kernel<<<ROWS, 256>>>(x1, ln2a, ln2b, xn2);

    gemm_tc<EPI_BIAS_RELU><<<dim3(DFF/BN, ROWS/BM), 256, GEMM_SMEM_BYTES>>>(
        xn2, fw1t, h1, fb1, nullptr, nullptr, nullptr, ROWS, DFF, DMODEL);
    gemm_tc<EPI_BIAS_RESID><<<dim3(DMODEL/BN, ROWS/BM), 256, GEMM_SMEM_BYTES>>>(
        h1, fw2t, out, fb2, x1, nullptr, nullptr, ROWS, DMODEL, DFF);

    mem_partial_kernel<<<dim3(BATCH, 16), 1024>>>(out, part);
    mem_final_kernel<<<BATCH, 1024>>>(part, out_mem);
}